// round 5
// baseline (speedup 1.0000x reference)
#include <cuda_runtime.h>
#include <math.h>

#define N_NODES 50000
#define N_EDGES 800000
#define F_NODE  92
#define F_EDGE  50
#define HID     128

// ---------------- scratch (static device globals) ---------------------------
__device__ float g_h[N_NODES * HID];
__device__ float g_Apack[N_NODES * 4 * HID];    // [node][512]: Afi|Afj|Asi|Asj
__device__ float g_agg[N_NODES * HID];
__device__ float g_Wpack[2 * HID * 4 * HID];    // packed proj weights [l][128][512]

// ---------------- tf32 helpers ----------------------------------------------
__device__ __forceinline__ unsigned f2tf32(float f) {
    unsigned u;
    asm("cvt.rna.tf32.f32 %0, %1;" : "=r"(u) : "f"(f));
    return u;
}

__device__ __forceinline__ void mma_tf32(float& d0, float& d1, float& d2, float& d3,
                                         unsigned a0, unsigned a1, unsigned a2, unsigned a3,
                                         unsigned b0, unsigned b1)
{
    asm volatile(
        "mma.sync.aligned.m16n8k8.row.col.f32.tf32.tf32.f32 "
        "{%0,%1,%2,%3}, {%4,%5,%6,%7}, {%8,%9}, {%0,%1,%2,%3};"
        : "+f"(d0), "+f"(d1), "+f"(d2), "+f"(d3)
        : "r"(a0), "r"(a1), "r"(a2), "r"(a3), "r"(b0), "r"(b1));
}

// ---------------- tf32 tensor-core GEMM: C = act(A[M,K]@B[K,N] (+bias)) ------
#define GBM 128
#define GBN 128
#define GKC 32

template<int ACT>  // 0 = none, 1 = relu
__global__ __launch_bounds__(256)
void gemm_tf32_kernel(const float* __restrict__ A, const float* __restrict__ B,
                      const float* __restrict__ bias, float* __restrict__ C,
                      int M, int N, int K)
{
    __shared__ float As[GKC][GBM + 1];
    __shared__ float Bs[GKC][GBN + 1];

    const int tid  = threadIdx.x;
    const int lane = tid & 31;
    const int warp = tid >> 5;
    const int g    = lane >> 2;
    const int t    = lane & 3;

    const int row0 = blockIdx.y * GBM;
    const int col0 = blockIdx.x * GBN;
    const int wr0  = (warp >> 1) * 32;
    const int wc0  = (warp & 1) * 64;

    float acc[2][8][4];
#pragma unroll
    for (int m = 0; m < 2; m++)
#pragma unroll
        for (int n = 0; n < 8; n++)
#pragma unroll
            for (int i = 0; i < 4; i++) acc[m][n][i] = 0.f;

    for (int k0 = 0; k0 < K; k0 += GKC) {
#pragma unroll
        for (int i = 0; i < (GBM * GKC) / 256; i++) {
            int idx = tid + i * 256;
            int r = idx >> 5;
            int c = idx & 31;
            int gr = row0 + r, gc = k0 + c;
            float v = 0.f;
            if (gr < M && gc < K) v = A[(long long)gr * K + gc];
            As[c][r] = __uint_as_float(f2tf32(v));
        }
#pragma unroll
        for (int i = 0; i < (GKC * GBN) / 256; i++) {
            int idx = tid + i * 256;
            int r = idx >> 7;
            int c = idx & 127;
            int gr = k0 + r, gc = col0 + c;
            float v = 0.f;
            if (gr < K && gc < N) v = B[(long long)gr * N + gc];
            Bs[r][c] = __uint_as_float(f2tf32(v));
        }
        __syncthreads();

#pragma unroll
        for (int kk = 0; kk < GKC / 8; kk++) {
            const int kb = kk * 8;
            unsigned a[2][4];
#pragma unroll
            for (int m = 0; m < 2; m++) {
                int r = wr0 + m * 16;
                a[m][0] = __float_as_uint(As[kb + t    ][r + g    ]);
                a[m][1] = __float_as_uint(As[kb + t    ][r + g + 8]);
                a[m][2] = __float_as_uint(As[kb + t + 4][r + g    ]);
                a[m][3] = __float_as_uint(As[kb + t + 4][r + g + 8]);
            }
#pragma unroll
            for (int n = 0; n < 8; n++) {
                int c = wc0 + n * 8 + g;
                unsigned b0 = __float_as_uint(Bs[kb + t    ][c]);
                unsigned b1 = __float_as_uint(Bs[kb + t + 4][c]);
#pragma unroll
                for (int m = 0; m < 2; m++)
                    mma_tf32(acc[m][n][0], acc[m][n][1], acc[m][n][2], acc[m][n][3],
                             a[m][0], a[m][1], a[m][2], a[m][3], b0, b1);
            }
        }
        __syncthreads();
    }

#pragma unroll
    for (int m = 0; m < 2; m++) {
#pragma unroll
        for (int n = 0; n < 8; n++) {
            int gc = col0 + wc0 + n * 8 + 2 * t;
            float bx = 0.f, by = 0.f;
            if (bias) { bx = bias[gc]; by = bias[gc + 1]; }

            int gr0 = row0 + wr0 + m * 16 + g;
            if (gr0 < M) {
                float v0 = acc[m][n][0] + bx;
                float v1 = acc[m][n][1] + by;
                if (ACT == 1) { v0 = fmaxf(v0, 0.f); v1 = fmaxf(v1, 0.f); }
                *reinterpret_cast<float2*>(&C[(long long)gr0 * N + gc]) = make_float2(v0, v1);
            }
            int gr1 = gr0 + 8;
            if (gr1 < M) {
                float v0 = acc[m][n][2] + bx;
                float v1 = acc[m][n][3] + by;
                if (ACT == 1) { v0 = fmaxf(v0, 0.f); v1 = fmaxf(v1, 0.f); }
                *reinterpret_cast<float2*>(&C[(long long)gr1 * N + gc]) = make_float2(v0, v1);
            }
        }
    }
}

// ---------------- weight pack -------------------------------------------------
__global__ void pack_weights_kernel(const float* __restrict__ Wf,
                                    const float* __restrict__ Ws,
                                    float* __restrict__ Wpack)
{
    int idx = blockIdx.x * 256 + threadIdx.x;
    if (idx >= 2 * 128 * 512) return;
    int l = idx >> 16;
    int k = (idx >> 9) & 127;
    int c = idx & 511;
    int sel = c >> 7;
    int j = c & 127;
    const float* W = (sel < 2) ? Wf : Ws;
    int row = (sel & 1) ? (128 + k) : k;
    Wpack[idx] = W[(long long)l * 306 * 128 + row * 128 + j];
}

// ---------------- copy kernel (agg = h) ---------------------------------------
__global__ void copy_kernel(const float* __restrict__ src, float* __restrict__ dst, int n4)
{
    int i = blockIdx.x * blockDim.x + threadIdx.x;
    if (i < n4) reinterpret_cast<float4*>(dst)[i] = reinterpret_cast<const float4*>(src)[i];
}

// ---------------- fused edge kernel: tensor-core projection --------------------
// Per block: 128 edges. pf/ps = ea[128x50] @ [Wfe|Wse][50x256] via tf32 mma,
// then per-fragment: + bias + gathered node projections, sigmoid*softplus,
// atomic scatter to agg[dst].
#define TE 128
#define EKP 56                 // K padded to 7 chunks of 8
#define AS_STRIDE 136          // row pad for conflict-free a-frag loads
#define BS_STRIDE 29           // float2 per col (28 + 1 pad)
#define EDGE_SM_FLOATS (EKP * AS_STRIDE + 256 * BS_STRIDE * 2 + 256)

__global__ __launch_bounds__(256, 1)
void edge_mma_kernel(const float* __restrict__ edge_attr,
                     const float* __restrict__ Wfe,   // [50][128]
                     const float* __restrict__ Wse,   // [50][128]
                     const float* __restrict__ bf_l,
                     const float* __restrict__ bs_l,
                     const float* __restrict__ Apack, // [N_NODES][512]
                     const int* __restrict__ src_idx,
                     const int* __restrict__ dst_idx,
                     float* __restrict__ agg)
{
    extern __shared__ float sm[];
    float*  As     = sm;                                        // [EKP][AS_STRIDE] : As[k][edge]
    float2* Bsp    = reinterpret_cast<float2*>(sm + EKP * AS_STRIDE);  // [256][BS_STRIDE]
    float*  bias_s = sm + EKP * AS_STRIDE + 256 * BS_STRIDE * 2;        // [256]

    const int tid  = threadIdx.x;
    const int lane = tid & 31;
    const int warp = tid >> 5;
    const int g    = lane >> 2;
    const int t    = lane & 3;
    const int e0   = blockIdx.x * TE;

    // ---- fill ea tile (transposed, tf32) ----
    {
        const float* ea = edge_attr + (long long)e0 * F_EDGE;
#pragma unroll
        for (int i = 0; i < (TE * F_EDGE) / 256; i++) {   // 25 iters
            int idx = tid + i * 256;
            int e = idx / F_EDGE;
            int k = idx - e * F_EDGE;
            As[k * AS_STRIDE + e] = __uint_as_float(f2tf32(ea[idx]));
        }
        // zero pad k = 50..55
#pragma unroll
        for (int i = 0; i < 3; i++) {
            int idx = tid + i * 256;      // < 768
            int k = F_EDGE + (idx >> 7);
            int r = idx & 127;
            As[k * AS_STRIDE + r] = 0.f;
        }
    }
    // ---- fill W tile: Bsp[c][kc*4+t] = {W[kc*8+t][c], W[kc*8+t+4][c]}, tf32 ----
#pragma unroll
    for (int i = 0; i < 28; i++) {
        int idx = tid + i * 256;          // < 7168
        int c  = idx / 28;
        int kk = idx - c * 28;
        int kc = kk >> 2;
        int tt = kk & 3;
        int k1 = kc * 8 + tt;
        int k2 = k1 + 4;
        const float* W = (c < 128) ? Wfe : Wse;
        int j = c & 127;
        float v1 = (k1 < F_EDGE) ? W[k1 * 128 + j] : 0.f;
        float v2 = (k2 < F_EDGE) ? W[k2 * 128 + j] : 0.f;
        Bsp[c * BS_STRIDE + kk] =
            make_float2(__uint_as_float(f2tf32(v1)), __uint_as_float(f2tf32(v2)));
    }
    if (tid < 128) {
        bias_s[tid]       = bf_l[tid];
        bias_s[128 + tid] = bs_l[tid];
    }
    __syncthreads();

    // ---- mma mainloop: each warp computes 16 edges x 256 outputs ----
    const int r0 = warp * 16;
    float acc[32][4];
#pragma unroll
    for (int n = 0; n < 32; n++)
#pragma unroll
        for (int i = 0; i < 4; i++) acc[n][i] = 0.f;

#pragma unroll
    for (int kc = 0; kc < 7; kc++) {
        const int kb = kc * 8;
        unsigned a0 = __float_as_uint(As[(kb + t    ) * AS_STRIDE + r0 + g    ]);
        unsigned a1 = __float_as_uint(As[(kb + t    ) * AS_STRIDE + r0 + g + 8]);
        unsigned a2 = __float_as_uint(As[(kb + t + 4) * AS_STRIDE + r0 + g    ]);
        unsigned a3 = __float_as_uint(As[(kb + t + 4) * AS_STRIDE + r0 + g + 8]);
#pragma unroll
        for (int n = 0; n < 32; n++) {
            float2 b = Bsp[(n * 8 + g) * BS_STRIDE + kc * 4 + t];
            mma_tf32(acc[n][0], acc[n][1], acc[n][2], acc[n][3],
                     a0, a1, a2, a3,
                     __float_as_uint(b.x), __float_as_uint(b.y));
        }
    }

    // ---- epilogue: gather + activation + scatter ----
    // acc[n][2q+0/1] = (edge r0+g+8q, cols n*8+2t, n*8+2t+1); n<16: f, n>=16: s
#pragma unroll
    for (int q = 0; q < 2; q++) {
        const int e = e0 + r0 + g + 8 * q;
        const int s = src_idx[e];
        const int d = dst_idx[e];
        const float* Ad = Apack + (long long)d * 512;
        const float* Aj = Apack + (long long)s * 512;
        float* aout = agg + (long long)d * HID;

#pragma unroll
        for (int n = 0; n < 16; n++) {
            const int col = n * 8 + 2 * t;
            const float2 afi = *reinterpret_cast<const float2*>(Ad + col);
            const float2 afj = *reinterpret_cast<const float2*>(Aj + 128 + col);
            const float2 asi = *reinterpret_cast<const float2*>(Ad + 256 + col);
            const float2 asj = *reinterpret_cast<const float2*>(Aj + 384 + col);

            float pf0 = acc[n][2 * q]      + bias_s[col]     + afi.x + afj.x;
            float pf1 = acc[n][2 * q + 1]  + bias_s[col + 1] + afi.y + afj.y;
            float ps0 = acc[n + 16][2 * q]     + bias_s[128 + col]     + asi.x + asj.x;
            float ps1 = acc[n + 16][2 * q + 1] + bias_s[128 + col + 1] + asi.y + asj.y;

            float m0 = (1.f / (1.f + __expf(-pf0))) *
                       (fmaxf(ps0, 0.f) + log1pf(__expf(-fabsf(ps0))));
            float m1 = (1.f / (1.f + __expf(-pf1))) *
                       (fmaxf(ps1, 0.f) + log1pf(__expf(-fabsf(ps1))));

            atomicAdd(aout + col,     m0);
            atomicAdd(aout + col + 1, m1);
        }
    }
}

// ---------------- launch --------------------------------------------------------
static inline void gemm_launch(int act, const float* A, const float* B,
                               const float* bias, float* C, int M, int N, int K)
{
    dim3 grid((N + GBN - 1) / GBN, (M + GBM - 1) / GBM);
    if (act == 1) gemm_tf32_kernel<1><<<grid, 256>>>(A, B, bias, C, M, N, K);
    else          gemm_tf32_kernel<0><<<grid, 256>>>(A, B, bias, C, M, N, K);
}

extern "C" void kernel_launch(void* const* d_in, const int* in_sizes, int n_in,
                              void* d_out, int out_size)
{
    const float* x         = (const float*)d_in[0];
    const float* edge_attr = (const float*)d_in[1];
    const float* W_in      = (const float*)d_in[2];
    const float* b_in      = (const float*)d_in[3];
    const float* Wf        = (const float*)d_in[4];
    const float* bf        = (const float*)d_in[5];
    const float* Ws        = (const float*)d_in[6];
    const float* bs        = (const float*)d_in[7];
    const float* Wm        = (const float*)d_in[8];
    const float* bm        = (const float*)d_in[9];
    const int*   ei        = (const int*)d_in[10];   // int32
    float* out = (float*)d_out;

    const int* src = ei;
    const int* dst = ei + N_EDGES;

    float* h;     cudaGetSymbolAddress((void**)&h,     g_h);
    float* Apack; cudaGetSymbolAddress((void**)&Apack, g_Apack);
    float* agg;   cudaGetSymbolAddress((void**)&agg,   g_agg);
    float* Wpack; cudaGetSymbolAddress((void**)&Wpack, g_Wpack);

    static bool smem_set = false;
    const int EDGE_SMEM = EDGE_SM_FLOATS * 4;   // ~90.9 KB
    if (!smem_set) {
        cudaFuncSetAttribute(edge_mma_kernel,
                             cudaFuncAttributeMaxDynamicSharedMemorySize, EDGE_SMEM);
        smem_set = true;
    }

    pack_weights_kernel<<<(2 * 128 * 512 + 255) / 256, 256>>>(Wf, Ws, Wpack);

    // h = relu(x @ W_in + b_in)
    gemm_launch(1, x, W_in, b_in, h, N_NODES, HID, F_NODE);

    for (int l = 0; l < 2; l++) {
        const float* Wfl = Wf + (long long)l * 306 * HID;
        const float* Wsl = Ws + (long long)l * 306 * HID;
        const float* bfl = bf + l * HID;
        const float* bsl = bs + l * HID;
        const float* Wml = Wm + (long long)l * HID * HID;
        const float* bml = bm + l * HID;
        const float* Wpl = Wpack + (long long)l * 128 * 512;

        // all 4 node projections in one GEMM: Apack = h @ Wpack_l  [50000 x 512]
        gemm_launch(0, h, Wpl, nullptr, Apack, N_NODES, 4 * HID, HID);

        // agg = h
        {
            int n4 = (N_NODES * HID) / 4;
            copy_kernel<<<(n4 + 255) / 256, 256>>>(h, agg, n4);
        }

        // fused: tensor-core edge projection + message + scatter-add
        edge_mma_kernel<<<N_EDGES / TE, 256, EDGE_SMEM>>>(
            edge_attr, Wfl + 256 * HID, Wsl + 256 * HID, bfl, bsl,
            Apack, src, dst, agg);

        // h = relu(agg @ Wm + bm); final layer writes to d_out
        float* hout = (l == 1) ? out : h;
        gemm_launch(1, agg, Wml, bml, hout, N_NODES, HID, HID);
    }
}